// round 7
// baseline (speedup 1.0000x reference)
#include <cuda_runtime.h>
#include <cuda_bf16.h>
#include <cstdint>

// ---------------------------------------------------------------------------
// RelGraphEmbedLayer:
//   out[i] = feat0[type_ids[i]] @ W0           if node_tids[i] == 0
//   out[i] = node_embed_table[node_ids[i]]      if node_tids[i] == 1
//
// kA: compaction into payload lists + W0 -> tf32 fragment pre-pack
// kB: fused single-pass tf32 mma GEMM (warp tile 64x64, 4 warps) +
//     embedding copy (1-in-8 blocks)
// ---------------------------------------------------------------------------

#define D_IN   256
#define EMBED  128
#define TILE_M 128

__device__ int  g_c0, g_c1, g_arrA;
__device__ int2 g_final;
__device__ int2 g_list0[1100000];     // (dst_row, feat0_row)
__device__ int2 g_list1[1100000];     // (dst_row, node_id)
// tf32 B fragments: [ktile(32)][tn(16)][lane(32)] -> uint2 {b0,b1}
__device__ uint2 g_Btf[16384];        // 128 KB (L1/L2-hot)

__device__ __forceinline__ long long load_idx(const void* p, int i, int is64) {
    if (is64) return ((const long long*)p)[i];
    return (long long)((const int*)p)[i];
}

__device__ __forceinline__ unsigned cvt_tf32(float x) {
    unsigned u;
    asm("cvt.rna.tf32.f32 %0, %1;" : "=r"(u) : "f"(x));
    return u;
}

__device__ __forceinline__ void mma_tf32(float* d, const uint4& a, const uint2& b) {
    asm volatile(
        "mma.sync.aligned.m16n8k8.row.col.f32.tf32.tf32.f32 "
        "{%0,%1,%2,%3}, {%4,%5,%6,%7}, {%8,%9}, {%0,%1,%2,%3};"
        : "+f"(d[0]), "+f"(d[1]), "+f"(d[2]), "+f"(d[3])
        : "r"(a.x), "r"(a.y), "r"(a.z), "r"(a.w), "r"(b.x), "r"(b.y));
}

// ---------------------------------------------------------------------------
// kA: blocks [0, cblocks): compaction. blocks [cblocks, cblocks+4): W0 pack.
// Last block publishes counts to g_final and zeroes counters (self-reset).
// ---------------------------------------------------------------------------
__global__ __launch_bounds__(256) void kA(
    const void* __restrict__ node_ids,
    const void* __restrict__ node_tids,
    const void* __restrict__ type_ids,
    const float* __restrict__ W0,
    int N, int cblocks, int gridTotal)
{
    const int b = blockIdx.x;
    const int t = threadIdx.x;

    if (b >= cblocks) {
        const int wb = b - cblocks;
        for (int f = wb * 256 + t; f < 16384; f += 1024) {
            const int kt  = f >> 9;
            const int tn  = (f >> 5) & 15;
            const int ln  = f & 31;
            const int sg  = ln >> 2;
            const int stc = ln & 3;
            const int col = tn * 8 + sg;
            float b0 = W0[(size_t)(kt * 8 + stc) * EMBED + col];
            float b1 = W0[(size_t)(kt * 8 + stc + 4) * EMBED + col];
            uint2 v;
            v.x = cvt_tf32(b0);
            v.y = cvt_tf32(b1);
            g_Btf[f] = v;
        }
    } else {
        const unsigned* w = (const unsigned*)node_ids;
        int is64 = 1;
        #pragma unroll
        for (int k = 0; k < 8; ++k)
            if (w[2 * k + 1] != 0u) { is64 = 0; break; }

        const int i    = b * 256 + t;
        const int lane = t & 31;
        const bool valid = i < N;
        long long tv = valid ? load_idx(node_tids, i, is64) : -1;
        const bool is0 = valid && (tv == 0);
        const bool is1 = valid && (tv != 0);

        unsigned m0 = __ballot_sync(0xffffffffu, is0);
        unsigned m1 = __ballot_sync(0xffffffffu, is1);
        int r0 = __popc(m0 & ((1u << lane) - 1u));
        int r1 = __popc(m1 & ((1u << lane) - 1u));
        int b0 = 0, b1 = 0;
        if (lane == 0) {
            if (m0) b0 = atomicAdd(&g_c0, __popc(m0));
            if (m1) b1 = atomicAdd(&g_c1, __popc(m1));
        }
        b0 = __shfl_sync(0xffffffffu, b0, 0);
        b1 = __shfl_sync(0xffffffffu, b1, 0);
        if (is0) {
            int2 e; e.x = i; e.y = (int)load_idx(type_ids, i, is64);
            g_list0[b0 + r0] = e;
        }
        if (is1) {
            int2 e; e.x = i; e.y = (int)load_idx(node_ids, i, is64);
            g_list1[b1 + r1] = e;
        }
    }

    __syncthreads();
    if (t == 0) {
        __threadfence();
        int old = atomicAdd(&g_arrA, 1);
        if (old == gridTotal - 1) {
            int2 f;
            f.x = atomicAdd(&g_c0, 0);
            f.y = atomicAdd(&g_c1, 0);
            g_final = f;
            g_c0 = 0;
            g_c1 = 0;
            g_arrA = 0;
            __threadfence();
        }
    }
}

// ---------------------------------------------------------------------------
// kB: 128 threads. blockIdx % 8 == 7 -> embed copy; else GEMM tile.
// GEMM: 128x128x256 tile, 4 warps (warp_m 0..1 x warp_n 0..1), warp 64x64.
// A double-buffered smem fragments + register prefetch; B direct LDG (hot).
// ---------------------------------------------------------------------------
__global__ __launch_bounds__(128, 2) void kB(
    const float* __restrict__ feat0,
    const float* __restrict__ table,
    float* __restrict__ out)
{
    const int2 counts = g_final;
    const int b = blockIdx.x;
    const int t = threadIdx.x;
    const int e = b >> 3;
    const int r = b & 7;
    const int lane = t & 31;
    const int wid  = t >> 5;

    if (r == 7) {
        // ---------------- embed copy (4 warps x 256 rows) ----------------
        const int c1 = counts.y;
        const int base = e * 1024 + wid * 256;
        if (base >= c1) return;
        for (int q = 0; q < 256; q += 4) {
            int2 pr[4]; float4 v[4]; bool ok[4];
            #pragma unroll
            for (int j = 0; j < 4; ++j) {
                const int idx = base + q + j;
                ok[j] = idx < c1;
                if (ok[j]) {
                    pr[j] = g_list1[idx];
                    v[j] = ((const float4*)(table + (size_t)pr[j].y * EMBED))[lane];
                }
            }
            #pragma unroll
            for (int j = 0; j < 4; ++j)
                if (ok[j])
                    ((float4*)(out + (size_t)pr[j].x * EMBED))[lane] = v[j];
        }
        return;
    }

    // ---------------- GEMM tile ----------------
    // A fragments double buffered: [buf][(m_tile*4 + ks)*32 + lane] uint4
    __shared__ uint4 sA[2][1024];      // 32 KB
    __shared__ int   s_cidx[TILE_M];
    __shared__ int   s_ridx[TILE_M];

    const int c0 = counts.x;
    const int go = 7 * e + r;
    const int m0 = go * TILE_M;
    if (m0 >= c0) return;
    const int rows = min(TILE_M, c0 - m0);

    const int warp_m = wid >> 1;       // 0..1
    const int warp_n = wid & 1;        // 0..1

    if (t < TILE_M) {
        const int src = (t < rows) ? (m0 + t) : m0;
        int2 pr = g_list0[src];
        s_cidx[t] = pr.x;
        s_ridx[t] = pr.y;
    }
    __syncthreads();

    // staging: thread (tm = t>>5 in 0..3, lane) owns rows 32*tm + sg + 8q,
    // q = 0..3 (m_tiles 2tm, 2tm+1), cols stc + 4j.
    const int tm  = t >> 5;
    const int sg  = lane >> 2;
    const int stc = lane & 3;
    const float* ap[4];
    #pragma unroll
    for (int q = 0; q < 4; ++q)
        ap[q] = feat0 + (size_t)s_ridx[tm * 32 + sg + 8 * q] * D_IN + stc;

    float acc[4][8][4];
    #pragma unroll
    for (int a = 0; a < 4; ++a)
        #pragma unroll
        for (int bb = 0; bb < 8; ++bb)
            #pragma unroll
            for (int c = 0; c < 4; ++c) acc[a][bb][c] = 0.0f;

    // prefetch chunk 0, stage it; prefetch chunk 1
    float f[4][8], nf[4][8];
    #pragma unroll
    for (int q = 0; q < 4; ++q)
        #pragma unroll
        for (int j = 0; j < 8; ++j) f[q][j] = ap[q][4 * j];

    #pragma unroll
    for (int ks = 0; ks < 4; ++ks) {
        uint4 fr0, fr1;
        fr0.x = cvt_tf32(f[0][2 * ks]);
        fr0.y = cvt_tf32(f[1][2 * ks]);
        fr0.z = cvt_tf32(f[0][2 * ks + 1]);
        fr0.w = cvt_tf32(f[1][2 * ks + 1]);
        fr1.x = cvt_tf32(f[2][2 * ks]);
        fr1.y = cvt_tf32(f[3][2 * ks]);
        fr1.z = cvt_tf32(f[2][2 * ks + 1]);
        fr1.w = cvt_tf32(f[3][2 * ks + 1]);
        sA[0][((2 * tm) * 4 + ks) * 32 + lane]     = fr0;
        sA[0][((2 * tm + 1) * 4 + ks) * 32 + lane] = fr1;
    }
    #pragma unroll
    for (int q = 0; q < 4; ++q)
        #pragma unroll
        for (int j = 0; j < 8; ++j) nf[q][j] = ap[q][32 + 4 * j];
    __syncthreads();

    #pragma unroll
    for (int c = 0; c < 8; ++c) {
        const int buf = c & 1;

        // ---- mma over chunk c: 4 ks x (4 mt x 8 nt) ----
        #pragma unroll
        for (int ks = 0; ks < 4; ++ks) {
            uint2 bb[8];
            #pragma unroll
            for (int nt = 0; nt < 8; ++nt)
                bb[nt] = g_Btf[(c * 4 + ks) * 512 + (warp_n * 8 + nt) * 32 + lane];
            uint4 aa[4];
            #pragma unroll
            for (int mt = 0; mt < 4; ++mt)
                aa[mt] = sA[buf][((warp_m * 4 + mt) * 4 + ks) * 32 + lane];
            #pragma unroll
            for (int mt = 0; mt < 4; ++mt)
                #pragma unroll
                for (int nt = 0; nt < 8; ++nt)
                    mma_tf32(acc[mt][nt], aa[mt], bb[nt]);
        }

        // ---- stage chunk c+1; prefetch chunk c+2 ----
        if (c < 7) {
            #pragma unroll
            for (int ks = 0; ks < 4; ++ks) {
                uint4 fr0, fr1;
                fr0.x = cvt_tf32(nf[0][2 * ks]);
                fr0.y = cvt_tf32(nf[1][2 * ks]);
                fr0.z = cvt_tf32(nf[0][2 * ks + 1]);
                fr0.w = cvt_tf32(nf[1][2 * ks + 1]);
                fr1.x = cvt_tf32(nf[2][2 * ks]);
                fr1.y = cvt_tf32(nf[3][2 * ks]);
                fr1.z = cvt_tf32(nf[2][2 * ks + 1]);
                fr1.w = cvt_tf32(nf[3][2 * ks + 1]);
                sA[buf ^ 1][((2 * tm) * 4 + ks) * 32 + lane]     = fr0;
                sA[buf ^ 1][((2 * tm + 1) * 4 + ks) * 32 + lane] = fr1;
            }
            if (c < 6) {
                #pragma unroll
                for (int q = 0; q < 4; ++q)
                    #pragma unroll
                    for (int j = 0; j < 8; ++j)
                        nf[q][j] = ap[q][32 * (c + 2) + 4 * j];
            }
        }
        __syncthreads();
    }

    // ---- epilogue: scatter from fragment layout ----
    const int g  = lane >> 2;
    const int tc = lane & 3;
    #pragma unroll
    for (int mt = 0; mt < 4; ++mt) {
        const int row0 = warp_m * 64 + mt * 16 + g;
        const int row1 = row0 + 8;
        float* o0 = (row0 < rows) ? (out + (size_t)s_cidx[row0] * EMBED) : nullptr;
        float* o1 = (row1 < rows) ? (out + (size_t)s_cidx[row1] * EMBED) : nullptr;
        #pragma unroll
        for (int nt = 0; nt < 8; ++nt) {
            const int col = warp_n * 64 + nt * 8 + tc * 2;
            if (o0) *(float2*)(o0 + col) = make_float2(acc[mt][nt][0], acc[mt][nt][1]);
            if (o1) *(float2*)(o1 + col) = make_float2(acc[mt][nt][2], acc[mt][nt][3]);
        }
    }
}

// ---------------------------------------------------------------------------
extern "C" void kernel_launch(void* const* d_in, const int* in_sizes, int n_in,
                              void* d_out, int out_size)
{
    const void*  node_ids    = d_in[0];
    const void*  node_tids   = d_in[1];
    const void*  type_ids    = d_in[2];
    const float* feat0       = (const float*)d_in[3];
    const float* W0          = (const float*)d_in[4];
    const float* embed_table = (const float*)d_in[5];
    float* out = (float*)d_out;

    const int N = in_sizes[0];

    const int cblocks = (N + 255) / 256;
    const int gridA   = cblocks + 4;
    kA<<<gridA, 256>>>(node_ids, node_tids, type_ids, W0, N, cblocks, gridA);

    const int gemmNeeded = (N + TILE_M - 1) / TILE_M;
    const int gridB = (gemmNeeded * 8 + 6) / 7 + 8;   // 1-in-8 blocks do embed
    kB<<<gridB, 128>>>(feat0, embed_table, out);
}

// round 8
// speedup vs baseline: 1.1407x; 1.1407x over previous
#include <cuda_runtime.h>
#include <cuda_bf16.h>
#include <cstdint>

// ---------------------------------------------------------------------------
// RelGraphEmbedLayer:
//   out[i] = feat0[type_ids[i]] @ W0           if node_tids[i] == 0
//   out[i] = node_embed_table[node_ids[i]]      if node_tids[i] == 1
//
// kA: compaction into payload lists + W0 -> tf32 fragment pre-pack
// kB: fused single-pass tf32 mma GEMM (8 warps, warp tile 64x32,
//     B-fragment register double-buffer) + embedding copy (1-in-8 blocks)
// ---------------------------------------------------------------------------

#define D_IN   256
#define EMBED  128
#define TILE_M 128

__device__ int  g_c0, g_c1, g_arrA;
__device__ int2 g_final;
__device__ int2 g_list0[1100000];     // (dst_row, feat0_row)
__device__ int2 g_list1[1100000];     // (dst_row, node_id)
// tf32 B fragments: [ktile(32)][tn(16)][lane(32)] -> uint2 {b0,b1}
__device__ uint2 g_Btf[16384];        // 128 KB (L2-resident)

__device__ __forceinline__ long long load_idx(const void* p, int i, int is64) {
    if (is64) return ((const long long*)p)[i];
    return (long long)((const int*)p)[i];
}

__device__ __forceinline__ unsigned cvt_tf32(float x) {
    unsigned u;
    asm("cvt.rna.tf32.f32 %0, %1;" : "=r"(u) : "f"(x));
    return u;
}

__device__ __forceinline__ void mma_tf32(float* d, const uint4& a, const uint2& b) {
    asm volatile(
        "mma.sync.aligned.m16n8k8.row.col.f32.tf32.tf32.f32 "
        "{%0,%1,%2,%3}, {%4,%5,%6,%7}, {%8,%9}, {%0,%1,%2,%3};"
        : "+f"(d[0]), "+f"(d[1]), "+f"(d[2]), "+f"(d[3])
        : "r"(a.x), "r"(a.y), "r"(a.z), "r"(a.w), "r"(b.x), "r"(b.y));
}

// ---------------------------------------------------------------------------
// kA: blocks [0, cblocks): compaction. blocks [cblocks, cblocks+4): W0 pack.
// Last block publishes counts to g_final and zeroes counters (self-reset).
// ---------------------------------------------------------------------------
__global__ __launch_bounds__(256) void kA(
    const void* __restrict__ node_ids,
    const void* __restrict__ node_tids,
    const void* __restrict__ type_ids,
    const float* __restrict__ W0,
    int N, int cblocks, int gridTotal)
{
    const int b = blockIdx.x;
    const int t = threadIdx.x;

    if (b >= cblocks) {
        const int wb = b - cblocks;
        for (int f = wb * 256 + t; f < 16384; f += 1024) {
            const int kt  = f >> 9;
            const int tn  = (f >> 5) & 15;
            const int ln  = f & 31;
            const int sg  = ln >> 2;
            const int stc = ln & 3;
            const int col = tn * 8 + sg;
            float b0 = W0[(size_t)(kt * 8 + stc) * EMBED + col];
            float b1 = W0[(size_t)(kt * 8 + stc + 4) * EMBED + col];
            uint2 v;
            v.x = cvt_tf32(b0);
            v.y = cvt_tf32(b1);
            g_Btf[f] = v;
        }
    } else {
        const unsigned* w = (const unsigned*)node_ids;
        int is64 = 1;
        #pragma unroll
        for (int k = 0; k < 8; ++k)
            if (w[2 * k + 1] != 0u) { is64 = 0; break; }

        const int i    = b * 256 + t;
        const int lane = t & 31;
        const bool valid = i < N;
        long long tv = valid ? load_idx(node_tids, i, is64) : -1;
        const bool is0 = valid && (tv == 0);
        const bool is1 = valid && (tv != 0);

        unsigned m0 = __ballot_sync(0xffffffffu, is0);
        unsigned m1 = __ballot_sync(0xffffffffu, is1);
        int r0 = __popc(m0 & ((1u << lane) - 1u));
        int r1 = __popc(m1 & ((1u << lane) - 1u));
        int b0 = 0, b1 = 0;
        if (lane == 0) {
            if (m0) b0 = atomicAdd(&g_c0, __popc(m0));
            if (m1) b1 = atomicAdd(&g_c1, __popc(m1));
        }
        b0 = __shfl_sync(0xffffffffu, b0, 0);
        b1 = __shfl_sync(0xffffffffu, b1, 0);
        if (is0) {
            int2 e; e.x = i; e.y = (int)load_idx(type_ids, i, is64);
            g_list0[b0 + r0] = e;
        }
        if (is1) {
            int2 e; e.x = i; e.y = (int)load_idx(node_ids, i, is64);
            g_list1[b1 + r1] = e;
        }
    }

    __syncthreads();
    if (t == 0) {
        __threadfence();
        int old = atomicAdd(&g_arrA, 1);
        if (old == gridTotal - 1) {
            int2 f;
            f.x = atomicAdd(&g_c0, 0);
            f.y = atomicAdd(&g_c1, 0);
            g_final = f;
            g_c0 = 0;
            g_c1 = 0;
            g_arrA = 0;
            __threadfence();
        }
    }
}

// ---------------------------------------------------------------------------
// kB: blockIdx % 8 == 7 -> embed-copy block; else GEMM tile.
// GEMM: 128x128x256 tile, 8 warps (warp_m 0..1 x warp_n 0..3), warp 64x32,
// single-pass tf32 mma, A double-buffered smem fragments,
// B direct LDG register-pipelined one k-step ahead.
// ---------------------------------------------------------------------------
__global__ __launch_bounds__(256, 2) void kB(
    const float* __restrict__ feat0,
    const float* __restrict__ table,
    float* __restrict__ out)
{
    const int2 counts = g_final;
    const int b = blockIdx.x;
    const int t = threadIdx.x;
    const int e = b >> 3;
    const int r = b & 7;
    const int lane = t & 31;
    const int wid  = t >> 5;

    if (r == 7) {
        // ---------------- embed copy ----------------
        const int c1 = counts.y;
        const int base = e * 1024 + wid * 128;
        if (base >= c1) return;
        for (int q = 0; q < 128; q += 4) {
            int2 pr[4]; float4 v[4]; bool ok[4];
            #pragma unroll
            for (int j = 0; j < 4; ++j) {
                const int idx = base + q + j;
                ok[j] = idx < c1;
                if (ok[j]) {
                    pr[j] = g_list1[idx];
                    v[j] = ((const float4*)(table + (size_t)pr[j].y * EMBED))[lane];
                }
            }
            #pragma unroll
            for (int j = 0; j < 4; ++j)
                if (ok[j])
                    ((float4*)(out + (size_t)pr[j].x * EMBED))[lane] = v[j];
        }
        return;
    }

    // ---------------- GEMM tile ----------------
    __shared__ uint4 sA[2][1024];      // 32 KB
    __shared__ int   s_cidx[TILE_M];
    __shared__ int   s_ridx[TILE_M];

    const int c0 = counts.x;
    const int go = 7 * e + r;
    const int m0 = go * TILE_M;
    if (m0 >= c0) return;
    const int rows = min(TILE_M, c0 - m0);

    const int warp_m = wid >> 2;       // 0..1
    const int warp_n = wid & 3;        // 0..3

    if (t < TILE_M) {
        const int src = (t < rows) ? (m0 + t) : m0;
        int2 pr = g_list0[src];
        s_cidx[t] = pr.x;
        s_ridx[t] = pr.y;
    }
    __syncthreads();

    const int tm  = t >> 5;            // 0..7
    const int sg  = lane >> 2;
    const int stc = lane & 3;
    const float* ap0 = feat0 + (size_t)s_ridx[tm * 16 + sg] * D_IN + stc;
    const float* ap1 = feat0 + (size_t)s_ridx[tm * 16 + sg + 8] * D_IN + stc;

    float acc[4][4][4];
    #pragma unroll
    for (int a = 0; a < 4; ++a)
        #pragma unroll
        for (int bb = 0; bb < 4; ++bb)
            #pragma unroll
            for (int c = 0; c < 4; ++c) acc[a][bb][c] = 0.0f;

    // prefetch chunk 0 and stage it; prefetch chunk 1
    float f0[8], f1[8], n0[8], n1[8];
    #pragma unroll
    for (int j = 0; j < 8; ++j) {
        f0[j] = ap0[4 * j];
        f1[j] = ap1[4 * j];
    }
    #pragma unroll
    for (int ks = 0; ks < 4; ++ks) {
        uint4 fr;
        fr.x = cvt_tf32(f0[2 * ks]);
        fr.y = cvt_tf32(f1[2 * ks]);
        fr.z = cvt_tf32(f0[2 * ks + 1]);
        fr.w = cvt_tf32(f1[2 * ks + 1]);
        sA[0][(tm * 4 + ks) * 32 + lane] = fr;
    }
    #pragma unroll
    for (int j = 0; j < 8; ++j) {
        n0[j] = ap0[32 + 4 * j];
        n1[j] = ap1[32 + 4 * j];
    }
    __syncthreads();

    const uint2* bbase = g_Btf + warp_n * 4 * 32 + lane;

    #pragma unroll
    for (int c = 0; c < 8; ++c) {
        const int buf = c & 1;

        // ---- mma over chunk c, B register-pipelined one ks ahead ----
        uint2 bb[2][4];
        #pragma unroll
        for (int nt = 0; nt < 4; ++nt)
            bb[0][nt] = bbase[(c * 4 + 0) * 512 + nt * 32];

        #pragma unroll
        for (int ks = 0; ks < 4; ++ks) {
            const int pb = ks & 1;
            if (ks < 3) {
                #pragma unroll
                for (int nt = 0; nt < 4; ++nt)
                    bb[pb ^ 1][nt] = bbase[(c * 4 + ks + 1) * 512 + nt * 32];
            }
            #pragma unroll
            for (int mt = 0; mt < 4; ++mt) {
                uint4 a = sA[buf][((warp_m * 4 + mt) * 4 + ks) * 32 + lane];
                #pragma unroll
                for (int nt = 0; nt < 4; ++nt)
                    mma_tf32(acc[mt][nt], a, bb[pb][nt]);
            }
        }

        // ---- stage chunk c+1 into other buffer; prefetch chunk c+2 ----
        if (c < 7) {
            #pragma unroll
            for (int ks = 0; ks < 4; ++ks) {
                uint4 fr;
                fr.x = cvt_tf32(n0[2 * ks]);
                fr.y = cvt_tf32(n1[2 * ks]);
                fr.z = cvt_tf32(n0[2 * ks + 1]);
                fr.w = cvt_tf32(n1[2 * ks + 1]);
                sA[buf ^ 1][(tm * 4 + ks) * 32 + lane] = fr;
            }
            if (c < 6) {
                #pragma unroll
                for (int j = 0; j < 8; ++j) {
                    n0[j] = ap0[32 * (c + 2) + 4 * j];
                    n1[j] = ap1[32 * (c + 2) + 4 * j];
                }
            }
        }
        __syncthreads();
    }

    // ---- epilogue: scatter from fragment layout ----
    const int g  = lane >> 2;
    const int tc = lane & 3;
    #pragma unroll
    for (int mt = 0; mt < 4; ++mt) {
        const int row0 = warp_m * 64 + mt * 16 + g;
        const int row1 = row0 + 8;
        float* o0 = (row0 < rows) ? (out + (size_t)s_cidx[row0] * EMBED) : nullptr;
        float* o1 = (row1 < rows) ? (out + (size_t)s_cidx[row1] * EMBED) : nullptr;
        #pragma unroll
        for (int nt = 0; nt < 4; ++nt) {
            const int col = warp_n * 32 + nt * 8 + tc * 2;
            if (o0) *(float2*)(o0 + col) = make_float2(acc[mt][nt][0], acc[mt][nt][1]);
            if (o1) *(float2*)(o1 + col) = make_float2(acc[mt][nt][2], acc[mt][nt][3]);
        }
    }
}

// ---------------------------------------------------------------------------
extern "C" void kernel_launch(void* const* d_in, const int* in_sizes, int n_in,
                              void* d_out, int out_size)
{
    const void*  node_ids    = d_in[0];
    const void*  node_tids   = d_in[1];
    const void*  type_ids    = d_in[2];
    const float* feat0       = (const float*)d_in[3];
    const float* W0          = (const float*)d_in[4];
    const float* embed_table = (const float*)d_in[5];
    float* out = (float*)d_out;

    const int N = in_sizes[0];

    const int cblocks = (N + 255) / 256;
    const int gridA   = cblocks + 4;
    kA<<<gridA, 256>>>(node_ids, node_tids, type_ids, W0, N, cblocks, gridA);

    const int gemmNeeded = (N + TILE_M - 1) / TILE_M;
    const int gridB = (gemmNeeded * 8 + 6) / 7 + 8;   // 1-in-8 blocks do embed
    kB<<<gridB, 256>>>(feat0, embed_table, out);
}